// round 13
// baseline (speedup 1.0000x reference)
#include <cuda_runtime.h>
#include <cuda_bf16.h>
#include <math.h>

// ---------------------------------------------------------------------------
// N=1024 nodes, F=128, H=256, complete graph.
//  - GIN aggregation on triu edges == inclusive prefix-sum over rows.
//  - cumsum(X) @ W == cumsum(X @ W)  -> GEMM first, scan after.
//  - leaky(relu(z)) == relu(z).
//  - Edge MLP: hidden = A[src] + B[dst], A = x@ew1[:F]+eb1, B = x@ew1[F:].
// R13: split-K x2 on K=256 GEMMs (256 CTAs -> 16 warps/SM) with cp.async-B
//      4-stage pipeline + LDG-A double buffer carrying the consumer-fused
//      partial combines (relu/leaky/bias). FFMA2 mainloop retained.
// ---------------------------------------------------------------------------

#define NN 1024
#define HH 256

__device__ float g_s0[NN * HH];
__device__ float g_s1[NN * HH];
__device__ float g_s2[NN * HH];
__device__ float g_s3[NN * HH];
__device__ float g_s4[NN * HH];
__device__ float g_s5[NN * HH];

typedef unsigned long long u64;

// ---- packed f32x2 helpers (sm_100a) ---------------------------------------
__device__ __forceinline__ u64 add2(u64 a, u64 b) {
    u64 r; asm("add.rn.f32x2 %0, %1, %2;" : "=l"(r) : "l"(a), "l"(b)); return r;
}
__device__ __forceinline__ u64 fma2(u64 a, u64 b, u64 c) {
    u64 r; asm("fma.rn.f32x2 %0, %1, %2, %3;" : "=l"(r) : "l"(a), "l"(b), "l"(c)); return r;
}
__device__ __forceinline__ u64 relu2(u64 t) {
    unsigned lo, hi;
    asm("mov.b64 {%0, %1}, %2;" : "=r"(lo), "=r"(hi) : "l"(t));
    float flo = fmaxf(__uint_as_float(lo), 0.f);
    float fhi = fmaxf(__uint_as_float(hi), 0.f);
    u64 r;
    asm("mov.b64 %0, {%1, %2};" : "=l"(r)
        : "r"(__float_as_uint(flo)), "r"(__float_as_uint(fhi)));
    return r;
}
__device__ __forceinline__ float sum2(u64 t) {
    unsigned lo, hi;
    asm("mov.b64 {%0, %1}, %2;" : "=r"(lo), "=r"(hi) : "l"(t));
    return __uint_as_float(lo) + __uint_as_float(hi);
}
__device__ __forceinline__ u64 dup2(float a) {
    u64 r; unsigned u = __float_as_uint(a);
    asm("mov.b64 %0, {%1, %1};" : "=l"(r) : "r"(u));
    return r;
}
__device__ __forceinline__ void unpack2(u64 t, float& lo, float& hi) {
    unsigned a, b;
    asm("mov.b64 {%0, %1}, %2;" : "=r"(a), "=r"(b) : "l"(t));
    lo = __uint_as_float(a); hi = __uint_as_float(b);
}

// ---- cp.async helpers ------------------------------------------------------
__device__ __forceinline__ void cpa16(unsigned dst, const void* src) {
    asm volatile("cp.async.cg.shared.global [%0], [%1], 16;" :: "r"(dst), "l"(src));
}
#define CPA_COMMIT() asm volatile("cp.async.commit_group;")
#define CPA_WAIT2()  asm volatile("cp.async.wait_group 2;")

// ---------------------------------------------------------------------------
// GEMM v13: out = actA(X0 [+X1] [+ab]) @ W (+bias), 256 threads, TM=32.
// B via 4-stage cp.async; A via LDG->combine->STS double buffer (carries the
// split-K partial combine + bias + activation of the PRODUCER GEMM).
// SPLIT: z&1 selects K-half; partials to out/outP (bias deferred downstream).
// DUAL:  z selects (W,out)/(W2,out2) — edge-feature pair (never with SPLIT).
// NX: #A inputs (1/2). ACT: 0 none, 1 relu, 2 leaky. AB: add ab[k] pre-act.
// ---------------------------------------------------------------------------
#define GAP 36                                   // A row pitch (floats)
#define GNS 4                                    // B pipeline stages

template <int K, int N, int TN, int NX, int ACT, int AB, int SPLIT, int DUAL>
__global__ __launch_bounds__(256) void sgemm13(
    const float* __restrict__ X0, const float* __restrict__ X1,
    const float* __restrict__ ab,
    const float* __restrict__ W, const float* __restrict__ W2,
    const float* __restrict__ bias,
    float* __restrict__ out, float* __restrict__ outP,
    float* __restrict__ out2, float* __restrict__ out2P) {

    constexpr int TK  = 32;
    constexpr int KB  = SPLIT ? K / 2 : K;        // K per block
    constexpr int NIT = KB / TK;                  // 4 or 8
    constexpr int NJ2 = TN / 32;                  // u64 cols per thread
    constexpr int WCH = TN / 32;                  // B 16B chunks per thread

    extern __shared__ float sh[];
    float* Asm = sh;                              // GNS*32*GAP
    float* Bsm = sh + GNS * 32 * GAP;             // GNS*TK*TN

    const int t  = threadIdx.x;
    const int tx = t & 15;
    const int ty = t >> 4;
    const int m0 = blockIdx.y * 32;
    const int n0 = blockIdx.x * TN;

    const int z    = blockIdx.z;
    const int half = SPLIT ? (z & 1) : 0;
    const int dsel = DUAL ? z : 0;
    const int koff = half * KB;

    const float* Wp = W;
    const float* bp = bias;
    float* op = out;
    if (DUAL && dsel) { Wp = W2; bp = nullptr; op = out2; (void)out2P; }
    else if (SPLIT && half) { op = outP; }

    const int am  = t >> 3;                       // 0..31 (A row)
    const int akc = (t & 7) * 4;                  // A k offset (float4)
    int br[WCH], bc[WCH];
#pragma unroll
    for (int p = 0; p < WCH; p++) {
        int q = (t + 256 * p);
        br[p] = q / (TN / 4);
        bc[p] = (q % (TN / 4)) * 4;
    }

    unsigned bSh = (unsigned)__cvta_generic_to_shared(Bsm);

    auto issueB = [&](int tile) {
        const int s  = tile & (GNS - 1);
        const int k0 = koff + tile * TK;
#pragma unroll
        for (int p = 0; p < WCH; p++)
            cpa16(bSh + (unsigned)(((s * TK + br[p]) * TN + bc[p]) * 4),
                  &Wp[(k0 + br[p]) * N + n0 + bc[p]]);
    };

    auto loadA = [&](int tile) -> float4 {
        const int kc = koff + tile * TK + akc;
        float4 v = *(const float4*)&X0[(m0 + am) * K + kc];
        if (NX == 2) {
            float4 u = *(const float4*)&X1[(m0 + am) * K + kc];
            v.x += u.x; v.y += u.y; v.z += u.z; v.w += u.w;
        }
        if (AB) {
            float4 bb = *(const float4*)&ab[kc];
            v.x += bb.x; v.y += bb.y; v.z += bb.z; v.w += bb.w;
        }
        if (ACT == 1) {
            v.x = fmaxf(v.x, 0.f); v.y = fmaxf(v.y, 0.f);
            v.z = fmaxf(v.z, 0.f); v.w = fmaxf(v.w, 0.f);
        } else if (ACT == 2) {
            v.x = (v.x >= 0.f) ? v.x : 0.01f * v.x;
            v.y = (v.y >= 0.f) ? v.y : 0.01f * v.y;
            v.z = (v.z >= 0.f) ? v.z : 0.01f * v.z;
            v.w = (v.w >= 0.f) ? v.w : 0.01f * v.w;
        }
        return v;
    };

    auto stsA = [&](int tile, float4 v) {
        const int s = tile & (GNS - 1);
        *(float4*)&Asm[(s * 32 + am) * GAP + akc] = v;
    };

    // Prologue: B tiles 0..2 via cp.async; A tile 0 staged, tile 1 in regs.
#pragma unroll
    for (int s = 0; s < GNS - 1; s++) { issueB(s); CPA_COMMIT(); }
    stsA(0, loadA(0));
    float4 aNext = (NIT > 1) ? loadA(1) : make_float4(0, 0, 0, 0);

    u64 acc[2][NJ2];
#pragma unroll
    for (int i = 0; i < 2; i++)
#pragma unroll
        for (int j = 0; j < NJ2; j++) acc[i][j] = 0ull;

#pragma unroll 1
    for (int it = 0; it < NIT; it++) {
        const int s = it & (GNS - 1);
        CPA_WAIT2();
        __syncthreads();
        const float* Ar0 = &Asm[(s * 32 + ty * 2 + 0) * GAP];
        const float* Ar1 = &Asm[(s * 32 + ty * 2 + 1) * GAP];
        const float* Bk  = &Bsm[s * TK * TN];
#pragma unroll
        for (int k4 = 0; k4 < TK; k4 += 4) {
            float4 a0v = *(const float4*)&Ar0[k4];
            float4 a1v = *(const float4*)&Ar1[k4];
#pragma unroll
            for (int kk = 0; kk < 4; kk++) {
                u64 a0d = dup2((&a0v.x)[kk]);
                u64 a1d = dup2((&a1v.x)[kk]);
                if (NJ2 == 2) {
                    ulonglong2 b = *(const ulonglong2*)&Bk[(k4 + kk) * TN + tx * 4];
                    acc[0][0] = fma2(a0d, b.x, acc[0][0]);
                    acc[0][1] = fma2(a0d, b.y, acc[0][1]);
                    acc[1][0] = fma2(a1d, b.x, acc[1][0]);
                    acc[1][1] = fma2(a1d, b.y, acc[1][1]);
                } else {
                    u64 b = *(const u64*)&Bk[(k4 + kk) * TN + tx * 2];
                    acc[0][0] = fma2(a0d, b, acc[0][0]);
                    acc[1][0] = fma2(a1d, b, acc[1][0]);
                }
            }
        }
        if (it + 1 < NIT) {
            stsA(it + 1, aNext);                  // consumed after next bar
            if (it + 2 < NIT) aNext = loadA(it + 2);
            issueB(it + GNS - 1 < NIT ? it + GNS - 1 : it + 1); // harmless re-issue guard
        }
        CPA_COMMIT();
    }

    constexpr int CPT = NJ2 * 2;
#pragma unroll
    for (int i = 0; i < 2; i++) {
        int m = m0 + ty * 2 + i;
#pragma unroll
        for (int j = 0; j < NJ2; j++) {
            float v0, v1;
            unpack2(acc[i][j], v0, v1);
            int n = n0 + tx * CPT + j * 2;
            if (bp) { v0 += bp[n]; v1 += bp[n + 1]; }
            op[m * N + n]     = v0;
            op[m * N + n + 1] = v1;
        }
    }
}

#define GEMM_SMEM(TN) ((GNS * 32 * GAP + GNS * 32 * (TN)) * 4)

// ---------------------------------------------------------------------------
// Column prefix-sum + BN + relu. Single-input and two-partial variants.
// ---------------------------------------------------------------------------
template <int NX>
__global__ void cumsum_k(const float* __restrict__ in0, const float* __restrict__ in1,
                         float* __restrict__ out,
                         const float* __restrict__ bias, const float* __restrict__ g,
                         const float* __restrict__ bt) {
    const int C = HH;
    const int c = blockIdx.x;
    const int t = threadIdx.x;
    __shared__ float ssum[256];

    float v[4];
    float run = 0.f;
    const int base = t * 4;
#pragma unroll
    for (int r = 0; r < 4; r++) {
        int idx = (base + r) * C + c;
        v[r] = (NX == 2) ? (in0[idx] + in1[idx]) : in0[idx];
        run += v[r];
        v[r] = run;
    }
    ssum[t] = run;
    __syncthreads();
    for (int off = 1; off < 256; off <<= 1) {
        float addv = 0.f;
        if (t >= off) addv = ssum[t - off];
        __syncthreads();
        if (t >= off) ssum[t] += addv;
        __syncthreads();
    }
    float excl = (t > 0) ? ssum[t - 1] : 0.f;
    float sc   = g[c] * rsqrtf(1.f + 1e-5f);
    float bb   = bias[c];
    float btc  = bt[c];
#pragma unroll
    for (int r = 0; r < 4; r++) {
        float h = (v[r] + excl + bb) * sc + btc;
        out[(base + r) * C + c] = fmaxf(h, 0.f);
    }
}

// ---------------------------------------------------------------------------
// Edge kernel: 64(i) x 32(j) pair tile, 256 threads, 4x2 micro, stride-16
// mapping, packed f32x2 + FMNMX relu. Active blocks: tj >= 2*ti.
// ---------------------------------------------------------------------------
#define ESA 256
#define ESB 260
#define EDGE_SMEM ((64 * ESA + 32 * ESB + 256) * 4)

__global__ __launch_bounds__(256) void edge_k(
    const float* __restrict__ A, const float* __restrict__ Bm,
    const float* __restrict__ ew2, const float* __restrict__ eb2,
    float* __restrict__ out) {
    const int ti = blockIdx.y, tj = blockIdx.x;
    if (tj < 2 * ti) return;

    extern __shared__ float sh[];
    float* As = sh;
    float* Bs = sh + 64 * ESA;
    float* ws = sh + 64 * ESA + 32 * ESB;

    const int t = threadIdx.x;
    ws[t] = ew2[t];

    const int i0 = ti * 64, j0 = tj * 32;
#pragma unroll
    for (int p = 0; p < 16; p++) {
        int q = t + 256 * p;
        int r = q >> 6;
        int c = (q & 63) << 2;
        *(float4*)&As[r * ESA + c] = *(const float4*)&A[(i0 + r) * HH + c];
    }
#pragma unroll
    for (int p = 0; p < 8; p++) {
        int q = t + 256 * p;
        int r = q >> 6;
        int c = (q & 63) << 2;
        *(float4*)&Bs[r * ESB + c] = *(const float4*)&Bm[(j0 + r) * HH + c];
    }
    __syncthreads();

    const int tx = t & 15, ty = t >> 4;

    u64 acc[4][2];
#pragma unroll
    for (int di = 0; di < 4; di++)
#pragma unroll
        for (int dj = 0; dj < 2; dj++) acc[di][dj] = 0ull;

#pragma unroll 2
    for (int h = 0; h < HH; h += 4) {
        u64 w01 = *(const u64*)&ws[h];
        u64 w23 = *(const u64*)&ws[h + 2];
        u64 a01[4], a23[4], b01[2], b23[2];
#pragma unroll
        for (int d = 0; d < 4; d++) {
            ulonglong2 av = *(const ulonglong2*)&As[(ty + 16 * d) * ESA + h];
            a01[d] = av.x; a23[d] = av.y;
        }
#pragma unroll
        for (int d = 0; d < 2; d++) {
            ulonglong2 bv = *(const ulonglong2*)&Bs[(tx + 16 * d) * ESB + h];
            b01[d] = bv.x; b23[d] = bv.y;
        }
#pragma unroll
        for (int di = 0; di < 4; di++) {
#pragma unroll
            for (int dj = 0; dj < 2; dj++) {
                acc[di][dj] = fma2(relu2(add2(a01[di], b01[dj])), w01, acc[di][dj]);
                acc[di][dj] = fma2(relu2(add2(a23[di], b23[dj])), w23, acc[di][dj]);
            }
        }
    }

    const float e2 = eb2[0];
#pragma unroll
    for (int di = 0; di < 4; di++) {
#pragma unroll
        for (int dj = 0; dj < 2; dj++) {
            int gi = i0 + ty + 16 * di;
            int gj = j0 + tx + 16 * dj;
            float s = sum2(acc[di][dj]) + e2;
            if (gi < gj) {
                float pv = 1.f / (1.f + __expf(-s));
                out[gi * NN + gj] = pv;
                out[gj * NN + gi] = pv;
            } else if (gi == gj) {
                out[gi * NN + gi] = 0.f;
            }
        }
    }
}

// ---------------------------------------------------------------------------
extern "C" void kernel_launch(void* const* d_in, const int* in_sizes, int n_in,
                              void* d_out, int out_size) {
    (void)in_sizes; (void)n_in; (void)out_size;
    const float* x0  = (const float*)d_in[0];
    const float* w1a = (const float*)d_in[1];
    const float* b1a = (const float*)d_in[2];
    const float* g1  = (const float*)d_in[3];
    const float* bt1 = (const float*)d_in[4];
    const float* w1b = (const float*)d_in[5];
    const float* b1b = (const float*)d_in[6];
    const float* w2a = (const float*)d_in[7];
    const float* b2a = (const float*)d_in[8];
    const float* g2  = (const float*)d_in[9];
    const float* bt2 = (const float*)d_in[10];
    const float* w2b = (const float*)d_in[11];
    const float* b2b = (const float*)d_in[12];
    const float* lw1 = (const float*)d_in[13];
    const float* lb1 = (const float*)d_in[14];
    const float* lw2 = (const float*)d_in[15];
    const float* lb2 = (const float*)d_in[16];
    const float* ew1 = (const float*)d_in[17];
    const float* eb1 = (const float*)d_in[18];
    const float* ew2 = (const float*)d_in[19];
    const float* eb2 = (const float*)d_in[20];
    float* out = (float*)d_out;

    float *S0, *S1, *S2, *S3, *S4, *S5;
    cudaGetSymbolAddress((void**)&S0, g_s0);
    cudaGetSymbolAddress((void**)&S1, g_s1);
    cudaGetSymbolAddress((void**)&S2, g_s2);
    cudaGetSymbolAddress((void**)&S3, g_s3);
    cudaGetSymbolAddress((void**)&S4, g_s4);
    cudaGetSymbolAddress((void**)&S5, g_s5);

    const dim3 blk(256);
    const dim3 gNS(4, 32);       // non-split -> 128 CTAs
    const dim3 gSP(4, 32, 2);    // split-K   -> 256 CTAs
    const dim3 gDU(4, 32, 2);    // dual      -> 256 CTAs
    const int s64 = GEMM_SMEM(64);
    const int s32 = GEMM_SMEM(32);

    (void)cudaFuncSetAttribute((sgemm13<128,256,64, 1,0,0, 0,0>), cudaFuncAttributeMaxDynamicSharedMemorySize, s64);
    (void)cudaFuncSetAttribute((sgemm13<256,256,64, 1,0,0, 1,0>), cudaFuncAttributeMaxDynamicSharedMemorySize, s64);
    (void)cudaFuncSetAttribute((sgemm13<256,256,64, 2,1,1, 1,0>), cudaFuncAttributeMaxDynamicSharedMemorySize, s64);
    (void)cudaFuncSetAttribute((sgemm13<256,128,32, 1,0,0, 1,0>), cudaFuncAttributeMaxDynamicSharedMemorySize, s32);
    (void)cudaFuncSetAttribute((sgemm13<128,256,64, 2,1,1, 0,0>), cudaFuncAttributeMaxDynamicSharedMemorySize, s64);
    (void)cudaFuncSetAttribute((sgemm13<256,128,32, 1,2,1, 1,0>), cudaFuncAttributeMaxDynamicSharedMemorySize, s32);
    (void)cudaFuncSetAttribute((sgemm13<128,256,64, 2,0,1, 0,1>), cudaFuncAttributeMaxDynamicSharedMemorySize, s64);
    (void)cudaFuncSetAttribute(edge_k, cudaFuncAttributeMaxDynamicSharedMemorySize, EDGE_SMEM);

    // G1: x0 @ w1a -> S0 ; cumsum+BN+relu -> S2
    sgemm13<128,256,64, 1,0,0, 0,0><<<gNS, blk, s64>>>(x0, nullptr, nullptr, w1a, nullptr, nullptr, S0, nullptr, nullptr, nullptr);
    cumsum_k<1><<<256, blk>>>(S0, nullptr, S2, b1a, g1, bt1);

    // G2 (split): S2 @ w1b -> S0,S1 (b1b deferred)
    sgemm13<256,256,64, 1,0,0, 1,0><<<gSP, blk, s64>>>(S2, nullptr, nullptr, w1b, nullptr, nullptr, S0, S1, nullptr, nullptr);

    // G3 (split): relu(S0+S1+b1b) @ w2a -> S3,S4 ; cumsum2+BN+relu -> S2
    sgemm13<256,256,64, 2,1,1, 1,0><<<gSP, blk, s64>>>(S0, S1, b1b, w2a, nullptr, nullptr, S3, S4, nullptr, nullptr);
    cumsum_k<2><<<256, blk>>>(S3, S4, S2, b2a, g2, bt2);

    // G4 (split): S2 @ w2b -> S0,S1 (b2b deferred)
    sgemm13<256,128,32, 1,0,0, 1,0><<<gSP, blk, s32>>>(S2, nullptr, nullptr, w2b, nullptr, nullptr, S0, S1, nullptr, nullptr);

    // G5: relu(S0+S1+b2b) @ lw1 -> S3 (lb1 deferred)
    sgemm13<128,256,64, 2,1,1, 0,0><<<gNS, blk, s64>>>(S0, S1, b2b, lw1, nullptr, nullptr, S3, nullptr, nullptr, nullptr);

    // G6 (split): leaky(S3+lb1) @ lw2 -> S0,S1 (lb2 deferred)
    sgemm13<256,128,32, 1,2,1, 1,0><<<gSP, blk, s32>>>(S3, nullptr, lb1, lw2, nullptr, nullptr, S0, S1, nullptr, nullptr);

    // G7 (dual): (S0+S1+lb2) @ ew1_lo + eb1 -> S2 ; @ ew1_hi -> S5
    sgemm13<128,256,64, 2,0,1, 0,1><<<gDU, blk, s64>>>(S0, S1, lb2, ew1, ew1 + 128 * HH, eb1, S2, nullptr, S5, nullptr);

    // Edge probabilities
    edge_k<<<dim3(32, 16), blk, EDGE_SMEM>>>(S2, S5, ew2, eb2, out);
}

// round 14
// speedup vs baseline: 1.0513x; 1.0513x over previous
#include <cuda_runtime.h>
#include <cuda_bf16.h>
#include <math.h>

// ---------------------------------------------------------------------------
// N=1024 nodes, F=128, H=256, complete graph.
//  - GIN aggregation on triu edges == inclusive prefix-sum over rows.
//  - cumsum(X) @ W == cumsum(X @ W)  -> GEMM first, scan after.
//  - leaky(relu(z)) == relu(z).
//  - Edge MLP: hidden = A[src] + B[dst], A = x@ew1[:F]+eb1, B = x@ew1[F:].
// R14 = R12 structure, but the two big GEMMs (K=256,N=256) use a 64x64-tile
//       4x4-micro kernel (2B smem/FMA vs 3B) with split-K x2 (128 CTAs) and
//       consumer-fused combines (proven in R13). Rest identical to R12.
// ---------------------------------------------------------------------------

#define NN 1024
#define HH 256

__device__ float g_s0[NN * HH];
__device__ float g_s1[NN * HH];
__device__ float g_s2[NN * HH];
__device__ float g_s3[NN * HH];
__device__ float g_s4[NN * HH];

typedef unsigned long long u64;

// ---- packed f32x2 helpers (sm_100a) ---------------------------------------
__device__ __forceinline__ u64 add2(u64 a, u64 b) {
    u64 r; asm("add.rn.f32x2 %0, %1, %2;" : "=l"(r) : "l"(a), "l"(b)); return r;
}
__device__ __forceinline__ u64 fma2(u64 a, u64 b, u64 c) {
    u64 r; asm("fma.rn.f32x2 %0, %1, %2, %3;" : "=l"(r) : "l"(a), "l"(b), "l"(c)); return r;
}
__device__ __forceinline__ u64 relu2(u64 t) {
    unsigned lo, hi;
    asm("mov.b64 {%0, %1}, %2;" : "=r"(lo), "=r"(hi) : "l"(t));
    float flo = fmaxf(__uint_as_float(lo), 0.f);
    float fhi = fmaxf(__uint_as_float(hi), 0.f);
    u64 r;
    asm("mov.b64 %0, {%1, %2};" : "=l"(r)
        : "r"(__float_as_uint(flo)), "r"(__float_as_uint(fhi)));
    return r;
}
__device__ __forceinline__ float sum2(u64 t) {
    unsigned lo, hi;
    asm("mov.b64 {%0, %1}, %2;" : "=r"(lo), "=r"(hi) : "l"(t));
    return __uint_as_float(lo) + __uint_as_float(hi);
}
__device__ __forceinline__ u64 dup2(float a) {
    u64 r; unsigned u = __float_as_uint(a);
    asm("mov.b64 %0, {%1, %1};" : "=l"(r) : "r"(u));
    return r;
}
__device__ __forceinline__ void unpack2(u64 t, float& lo, float& hi) {
    unsigned a, b;
    asm("mov.b64 {%0, %1}, %2;" : "=r"(a), "=r"(b) : "l"(t));
    lo = __uint_as_float(a); hi = __uint_as_float(b);
}

// ---- cp.async helpers ------------------------------------------------------
__device__ __forceinline__ void cpa16(unsigned dst, const void* src) {
    asm volatile("cp.async.cg.shared.global [%0], [%1], 16;" :: "r"(dst), "l"(src));
}
#define CPA_COMMIT() asm volatile("cp.async.commit_group;")
#define CPA_WAIT2()  asm volatile("cp.async.wait_group 2;")

#define GAP 36                                   // A row pitch (floats)
#define GNS 4                                    // pipeline stages

// ---------------------------------------------------------------------------
// sgemm11 (R12-proven): TM=32, TN in {64,32}, 2x(TN/16) micro, FFMA2,
// 4-stage cp.async for A and B. Used for the K=128 and N=128 GEMMs.
// DUAL: blockIdx.z==1 -> X@W2 -> out2 (no bias). EPI: 0 none,1 relu,2 leaky.
// ---------------------------------------------------------------------------
template <int K, int N, int TN, int EPI, int DUAL>
__global__ __launch_bounds__(256) void sgemm11(
    const float* __restrict__ X, const float* __restrict__ W,
    const float* __restrict__ W2, const float* __restrict__ bias,
    float* __restrict__ out, float* __restrict__ out2) {

    constexpr int TK  = 32;
    constexpr int NIT = K / TK;
    constexpr int NJ2 = TN / 32;
    constexpr int WCH = TN / 32;

    extern __shared__ float sh[];
    float* Asm = sh;
    float* Bsm = sh + GNS * 32 * GAP;

    const int t  = threadIdx.x;
    const int tx = t & 15;
    const int ty = t >> 4;
    const int m0 = blockIdx.y * 32;
    const int n0 = blockIdx.x * TN;

    const float* Wp = W;
    const float* bp = bias;
    float*       op = out;
    if (DUAL && blockIdx.z) { Wp = W2; bp = nullptr; op = out2; }

    const int am  = t >> 3;
    const int akc = (t & 7) * 4;
    int br[WCH], bc[WCH];
#pragma unroll
    for (int p = 0; p < WCH; p++) {
        int q = (t + 256 * p);
        br[p] = q / (TN / 4);
        bc[p] = (q % (TN / 4)) * 4;
    }

    unsigned aSh = (unsigned)__cvta_generic_to_shared(Asm);
    unsigned bSh = (unsigned)__cvta_generic_to_shared(Bsm);

    auto issueTile = [&](int tile) {
        const int s  = tile & (GNS - 1);
        const int k0 = tile * TK;
        cpa16(aSh + (unsigned)(((s * 32 + am) * GAP + akc) * 4),
              &X[(m0 + am) * K + k0 + akc]);
#pragma unroll
        for (int p = 0; p < WCH; p++)
            cpa16(bSh + (unsigned)(((s * TK + br[p]) * TN + bc[p]) * 4),
                  &Wp[(k0 + br[p]) * N + n0 + bc[p]]);
    };

#pragma unroll
    for (int s = 0; s < GNS - 1; s++) { issueTile(s); CPA_COMMIT(); }

    u64 acc[2][NJ2];
#pragma unroll
    for (int i = 0; i < 2; i++)
#pragma unroll
        for (int j = 0; j < NJ2; j++) acc[i][j] = 0ull;

#pragma unroll 1
    for (int it = 0; it < NIT; it++) {
        const int s = it & (GNS - 1);
        CPA_WAIT2();
        __syncthreads();
        const float* Ar0 = &Asm[(s * 32 + ty * 2 + 0) * GAP];
        const float* Ar1 = &Asm[(s * 32 + ty * 2 + 1) * GAP];
        const float* Bk  = &Bsm[s * TK * TN];
#pragma unroll
        for (int k4 = 0; k4 < TK; k4 += 4) {
            float4 a0v = *(const float4*)&Ar0[k4];
            float4 a1v = *(const float4*)&Ar1[k4];
#pragma unroll
            for (int kk = 0; kk < 4; kk++) {
                u64 a0d = dup2((&a0v.x)[kk]);
                u64 a1d = dup2((&a1v.x)[kk]);
                if (NJ2 == 2) {
                    ulonglong2 b = *(const ulonglong2*)&Bk[(k4 + kk) * TN + tx * 4];
                    acc[0][0] = fma2(a0d, b.x, acc[0][0]);
                    acc[0][1] = fma2(a0d, b.y, acc[0][1]);
                    acc[1][0] = fma2(a1d, b.x, acc[1][0]);
                    acc[1][1] = fma2(a1d, b.y, acc[1][1]);
                } else {
                    u64 b = *(const u64*)&Bk[(k4 + kk) * TN + tx * 2];
                    acc[0][0] = fma2(a0d, b, acc[0][0]);
                    acc[1][0] = fma2(a1d, b, acc[1][0]);
                }
            }
        }
        if (it + GNS - 1 < NIT) issueTile(it + GNS - 1);
        CPA_COMMIT();
    }

    constexpr int CPT = NJ2 * 2;
#pragma unroll
    for (int i = 0; i < 2; i++) {
        int m = m0 + ty * 2 + i;
#pragma unroll
        for (int j = 0; j < NJ2; j++) {
            float v0, v1;
            unpack2(acc[i][j], v0, v1);
            int n = n0 + tx * CPT + j * 2;
            if (bp) { v0 += bp[n]; v1 += bp[n + 1]; }
            if (EPI == 1) { v0 = fmaxf(v0, 0.f); v1 = fmaxf(v1, 0.f); }
            if (EPI == 2) {
                v0 = (v0 >= 0.f) ? v0 : 0.01f * v0;
                v1 = (v1 >= 0.f) ? v1 : 0.01f * v1;
            }
            op[m * N + n]     = v0;
            op[m * N + n + 1] = v1;
        }
    }
}

#define GEMM_SMEM(TN) ((GNS * 32 * GAP + GNS * 32 * (TN)) * 4)

// ---------------------------------------------------------------------------
// sgemm14: 64x64 tile, 256 threads, 4x4 micro (2B smem/FMA), split-K x2.
// out = actA(X0 [+X1] [+ab]) @ W, partials (no bias/epi). K=256, N=256 only.
// B via 4-stage cp.async; A via LDG->combine->STS (carries producer epilogue).
// Grid (4, 16, 2) = 128 CTAs; KB=128 -> 4 TK-iterations.
// ---------------------------------------------------------------------------
template <int NX, int ACT, int AB>
__global__ __launch_bounds__(256) void sgemm14(
    const float* __restrict__ X0, const float* __restrict__ X1,
    const float* __restrict__ ab, const float* __restrict__ W,
    float* __restrict__ out, float* __restrict__ outP) {

    constexpr int K   = 256;
    constexpr int N   = 256;
    constexpr int TK  = 32;
    constexpr int KB  = 128;
    constexpr int NIT = KB / TK;                  // 4

    extern __shared__ float sh[];
    float* Asm = sh;                              // GNS * 64 * GAP
    float* Bsm = sh + GNS * 64 * GAP;             // GNS * TK * 64

    const int t  = threadIdx.x;
    const int tx = t & 15;
    const int ty = t >> 4;
    const int m0 = blockIdx.y * 64;
    const int n0 = blockIdx.x * 64;
    const int half = blockIdx.z;
    const int koff = half * KB;
    float* op = half ? outP : out;

    // A chunks: 64 rows x 32 k = 512 float4 -> 2 per thread
    int ar[2], ac[2];
#pragma unroll
    for (int p = 0; p < 2; p++) {
        int q = t + 256 * p;
        ar[p] = q >> 3;
        ac[p] = (q & 7) * 4;
    }
    // B chunks: 32 k x 64 n = 512 float4 -> 2 per thread
    int br[2], bc[2];
#pragma unroll
    for (int p = 0; p < 2; p++) {
        int q = t + 256 * p;
        br[p] = q >> 4;
        bc[p] = (q & 15) * 4;
    }

    unsigned bSh = (unsigned)__cvta_generic_to_shared(Bsm);

    auto issueB = [&](int tile) {
        const int s  = tile & (GNS - 1);
        const int k0 = koff + tile * TK;
#pragma unroll
        for (int p = 0; p < 2; p++)
            cpa16(bSh + (unsigned)(((s * TK + br[p]) * 64 + bc[p]) * 4),
                  &W[(k0 + br[p]) * N + n0 + bc[p]]);
    };

    auto loadA = [&](int tile, float4* v) {
#pragma unroll
        for (int p = 0; p < 2; p++) {
            const int kc = koff + tile * TK + ac[p];
            float4 x = *(const float4*)&X0[(m0 + ar[p]) * K + kc];
            if (NX == 2) {
                float4 u = *(const float4*)&X1[(m0 + ar[p]) * K + kc];
                x.x += u.x; x.y += u.y; x.z += u.z; x.w += u.w;
            }
            if (AB) {
                float4 bb = *(const float4*)&ab[kc];
                x.x += bb.x; x.y += bb.y; x.z += bb.z; x.w += bb.w;
            }
            if (ACT == 1) {
                x.x = fmaxf(x.x, 0.f); x.y = fmaxf(x.y, 0.f);
                x.z = fmaxf(x.z, 0.f); x.w = fmaxf(x.w, 0.f);
            } else if (ACT == 2) {
                x.x = (x.x >= 0.f) ? x.x : 0.01f * x.x;
                x.y = (x.y >= 0.f) ? x.y : 0.01f * x.y;
                x.z = (x.z >= 0.f) ? x.z : 0.01f * x.z;
                x.w = (x.w >= 0.f) ? x.w : 0.01f * x.w;
            }
            v[p] = x;
        }
    };

    auto stsA = [&](int tile, const float4* v) {
        const int s = tile & (GNS - 1);
#pragma unroll
        for (int p = 0; p < 2; p++)
            *(float4*)&Asm[(s * 64 + ar[p]) * GAP + ac[p]] = v[p];
    };

    // Prologue
#pragma unroll
    for (int s = 0; s < GNS - 1; s++) { issueB(s); CPA_COMMIT(); }
    float4 aCur[2];
    loadA(0, aCur);
    stsA(0, aCur);
    float4 aNext[2];
    if (NIT > 1) loadA(1, aNext);

    u64 acc[4][2];
#pragma unroll
    for (int i = 0; i < 4; i++)
#pragma unroll
        for (int j = 0; j < 2; j++) acc[i][j] = 0ull;

#pragma unroll 1
    for (int it = 0; it < NIT; it++) {
        const int s = it & (GNS - 1);
        CPA_WAIT2();
        __syncthreads();
        const float* Ar0 = &Asm[(s * 64 + ty * 4 + 0) * GAP];
        const float* Ar1 = &Asm[(s * 64 + ty * 4 + 1) * GAP];
        const float* Ar2 = &Asm[(s * 64 + ty * 4 + 2) * GAP];
        const float* Ar3 = &Asm[(s * 64 + ty * 4 + 3) * GAP];
        const float* Bk  = &Bsm[s * TK * 64];
#pragma unroll
        for (int k4 = 0; k4 < TK; k4 += 4) {
            float4 av0 = *(const float4*)&Ar0[k4];
            float4 av1 = *(const float4*)&Ar1[k4];
            float4 av2 = *(const float4*)&Ar2[k4];
            float4 av3 = *(const float4*)&Ar3[k4];
#pragma unroll
            for (int kk = 0; kk < 4; kk++) {
                ulonglong2 b = *(const ulonglong2*)&Bk[(k4 + kk) * 64 + tx * 4];
                u64 d0 = dup2((&av0.x)[kk]);
                u64 d1 = dup2((&av1.x)[kk]);
                u64 d2 = dup2((&av2.x)[kk]);
                u64 d3 = dup2((&av3.x)[kk]);
                acc[0][0] = fma2(d0, b.x, acc[0][0]);
                acc[0][1] = fma2(d0, b.y, acc[0][1]);
                acc[1][0] = fma2(d1, b.x, acc[1][0]);
                acc[1][1] = fma2(d1, b.y, acc[1][1]);
                acc[2][0] = fma2(d2, b.x, acc[2][0]);
                acc[2][1] = fma2(d2, b.y, acc[2][1]);
                acc[3][0] = fma2(d3, b.x, acc[3][0]);
                acc[3][1] = fma2(d3, b.y, acc[3][1]);
            }
        }
        if (it + 1 < NIT) {
            stsA(it + 1, aNext);
            if (it + 2 < NIT) loadA(it + 2, aNext);
            if (it + GNS - 1 < NIT) issueB(it + GNS - 1);
        }
        CPA_COMMIT();
    }

#pragma unroll
    for (int i = 0; i < 4; i++) {
        int m = m0 + ty * 4 + i;
        int n = n0 + tx * 4;
        float v0, v1, v2, v3;
        unpack2(acc[i][0], v0, v1);
        unpack2(acc[i][1], v2, v3);
        *(float4*)&op[m * N + n] = make_float4(v0, v1, v2, v3);
    }
}

#define GEMM14_SMEM ((GNS * 64 * GAP + GNS * 32 * 64) * 4)

// ---------------------------------------------------------------------------
// Column prefix-sum + BN + relu (single-input and two-partial variants).
// ---------------------------------------------------------------------------
template <int NX>
__global__ void cumsum_k(const float* __restrict__ in0, const float* __restrict__ in1,
                         float* __restrict__ out,
                         const float* __restrict__ bias, const float* __restrict__ g,
                         const float* __restrict__ bt) {
    const int C = HH;
    const int c = blockIdx.x;
    const int t = threadIdx.x;
    __shared__ float ssum[256];

    float v[4];
    float run = 0.f;
    const int base = t * 4;
#pragma unroll
    for (int r = 0; r < 4; r++) {
        int idx = (base + r) * C + c;
        v[r] = (NX == 2) ? (in0[idx] + in1[idx]) : in0[idx];
        run += v[r];
        v[r] = run;
    }
    ssum[t] = run;
    __syncthreads();
    for (int off = 1; off < 256; off <<= 1) {
        float addv = 0.f;
        if (t >= off) addv = ssum[t - off];
        __syncthreads();
        if (t >= off) ssum[t] += addv;
        __syncthreads();
    }
    float excl = (t > 0) ? ssum[t - 1] : 0.f;
    float sc   = g[c] * rsqrtf(1.f + 1e-5f);
    float bb   = bias[c];
    float btc  = bt[c];
#pragma unroll
    for (int r = 0; r < 4; r++) {
        float h = (v[r] + excl + bb) * sc + btc;
        out[(base + r) * C + c] = fmaxf(h, 0.f);
    }
}

// ---------------------------------------------------------------------------
// Edge kernel (R12-proven): 64x32 tile, 256 threads, 4x2 micro, stride-16,
// packed f32x2 + FMNMX relu. Active blocks: tj >= 2*ti.
// ---------------------------------------------------------------------------
#define ESA 256
#define ESB 260
#define EDGE_SMEM ((64 * ESA + 32 * ESB + 256) * 4)

__global__ __launch_bounds__(256) void edge_k(
    const float* __restrict__ A, const float* __restrict__ Bm,
    const float* __restrict__ ew2, const float* __restrict__ eb2,
    float* __restrict__ out) {
    const int ti = blockIdx.y, tj = blockIdx.x;
    if (tj < 2 * ti) return;

    extern __shared__ float sh[];
    float* As = sh;
    float* Bs = sh + 64 * ESA;
    float* ws = sh + 64 * ESA + 32 * ESB;

    const int t = threadIdx.x;
    ws[t] = ew2[t];

    const int i0 = ti * 64, j0 = tj * 32;
#pragma unroll
    for (int p = 0; p < 16; p++) {
        int q = t + 256 * p;
        int r = q >> 6;
        int c = (q & 63) << 2;
        *(float4*)&As[r * ESA + c] = *(const float4*)&A[(i0 + r) * HH + c];
    }
#pragma unroll
    for (int p = 0; p < 8; p++) {
        int q = t + 256 * p;
        int r = q >> 6;
        int c = (q & 63) << 2;
        *(float4*)&Bs[r * ESB + c] = *(const float4*)&Bm[(j0 + r) * HH + c];
    }
    __syncthreads();

    const int tx = t & 15, ty = t >> 4;

    u64 acc[4][2];
#pragma unroll
    for (int di = 0; di < 4; di++)
#pragma unroll
        for (int dj = 0; dj < 2; dj++) acc[di][dj] = 0ull;

#pragma unroll 2
    for (int h = 0; h < HH; h += 4) {
        u64 w01 = *(const u64*)&ws[h];
        u64 w23 = *(const u64*)&ws[h + 2];
        u64 a01[4], a23[4], b01[2], b23[2];
#pragma unroll
        for (int d = 0; d < 4; d++) {
            ulonglong2 av = *(const ulonglong2*)&As[(ty + 16 * d) * ESA + h];
            a01[d] = av.x; a23[d] = av.y;
        }
#pragma unroll
        for (int d = 0; d < 2; d++) {
            ulonglong2 bv = *(const ulonglong2*)&Bs[(tx + 16 * d) * ESB + h];
            b01[d] = bv.x; b23[d] = bv.y;
        }
#pragma unroll
        for (int di = 0; di < 4; di++) {
#pragma unroll
            for (int dj = 0; dj < 2; dj++) {
                acc[di][dj] = fma2(relu2(add2(a01[di], b01[dj])), w01, acc[di][dj]);
                acc[di][dj] = fma2(relu2(add2(a23[di], b23[dj])), w23, acc[di][dj]);
            }
        }
    }

    const float e2 = eb2[0];
#pragma unroll
    for (int di = 0; di < 4; di++) {
#pragma unroll
        for (int dj = 0; dj < 2; dj++) {
            int gi = i0 + ty + 16 * di;
            int gj = j0 + tx + 16 * dj;
            float s = sum2(acc[di][dj]) + e2;
            if (gi < gj) {
                float pv = 1.f / (1.f + __expf(-s));
                out[gi * NN + gj] = pv;
                out[gj * NN + gi] = pv;
            } else if (gi == gj) {
                out[gi * NN + gi] = 0.f;
            }
        }
    }
}

// ---------------------------------------------------------------------------
extern "C" void kernel_launch(void* const* d_in, const int* in_sizes, int n_in,
                              void* d_out, int out_size) {
    (void)in_sizes; (void)n_in; (void)out_size;
    const float* x0  = (const float*)d_in[0];
    const float* w1a = (const float*)d_in[1];
    const float* b1a = (const float*)d_in[2];
    const float* g1  = (const float*)d_in[3];
    const float* bt1 = (const float*)d_in[4];
    const float* w1b = (const float*)d_in[5];
    const float* b1b = (const float*)d_in[6];
    const float* w2a = (const float*)d_in[7];
    const float* b2a = (const float*)d_in[8];
    const float* g2  = (const float*)d_in[9];
    const float* bt2 = (const float*)d_in[10];
    const float* w2b = (const float*)d_in[11];
    const float* b2b = (const float*)d_in[12];
    const float* lw1 = (const float*)d_in[13];
    const float* lb1 = (const float*)d_in[14];
    const float* lw2 = (const float*)d_in[15];
    const float* lb2 = (const float*)d_in[16];
    const float* ew1 = (const float*)d_in[17];
    const float* eb1 = (const float*)d_in[18];
    const float* ew2 = (const float*)d_in[19];
    const float* eb2 = (const float*)d_in[20];
    float* out = (float*)d_out;

    float *S0, *S1, *S2, *S3, *S4;
    cudaGetSymbolAddress((void**)&S0, g_s0);
    cudaGetSymbolAddress((void**)&S1, g_s1);
    cudaGetSymbolAddress((void**)&S2, g_s2);
    cudaGetSymbolAddress((void**)&S3, g_s3);
    cudaGetSymbolAddress((void**)&S4, g_s4);

    const dim3 blk(256);
    const dim3 gA(4, 32);        // sgemm11 N=256 -> 128 blocks
    const dim3 gB(4, 32);        // sgemm11 N=128 -> 128 blocks
    const dim3 gD(4, 32, 2);     // dual edge GEMM -> 256 blocks
    const dim3 gF(4, 16, 2);     // sgemm14 split 64x64 -> 128 blocks
    const int s64 = GEMM_SMEM(64);
    const int s32 = GEMM_SMEM(32);
    const int sF  = GEMM14_SMEM;

    (void)cudaFuncSetAttribute((sgemm11<128, 256, 64, 0, 0>), cudaFuncAttributeMaxDynamicSharedMemorySize, s64);
    (void)cudaFuncSetAttribute((sgemm11<256, 128, 32, 1, 0>), cudaFuncAttributeMaxDynamicSharedMemorySize, s32);
    (void)cudaFuncSetAttribute((sgemm11<128, 256, 64, 2, 0>), cudaFuncAttributeMaxDynamicSharedMemorySize, s64);
    (void)cudaFuncSetAttribute((sgemm11<256, 128, 32, 0, 0>), cudaFuncAttributeMaxDynamicSharedMemorySize, s32);
    (void)cudaFuncSetAttribute((sgemm11<128, 256, 64, 0, 1>), cudaFuncAttributeMaxDynamicSharedMemorySize, s64);
    (void)cudaFuncSetAttribute((sgemm14<1, 0, 0>), cudaFuncAttributeMaxDynamicSharedMemorySize, sF);
    (void)cudaFuncSetAttribute((sgemm14<2, 1, 1>), cudaFuncAttributeMaxDynamicSharedMemorySize, sF);
    (void)cudaFuncSetAttribute(edge_k, cudaFuncAttributeMaxDynamicSharedMemorySize, EDGE_SMEM);

    // G1: x0 @ w1a -> S0 ; cumsum+BN+relu -> S2
    sgemm11<128, 256, 64, 0, 0><<<gA, blk, s64>>>(x0, w1a, nullptr, nullptr, S0, nullptr);
    cumsum_k<1><<<256, blk>>>(S0, nullptr, S2, b1a, g1, bt1);

    // G2 (64x64 split): S2 @ w1b -> S0,S1 (relu+b1b deferred to G3)
    sgemm14<1, 0, 0><<<gF, blk, sF>>>(S2, nullptr, nullptr, w1b, S0, S1);

    // G3 (64x64 split): relu(S0+S1+b1b) @ w2a -> S3,S4 ; cumsum2 -> S2
    sgemm14<2, 1, 1><<<gF, blk, sF>>>(S0, S1, b1b, w2a, S3, S4);
    cumsum_k<2><<<256, blk>>>(S3, S4, S2, b2a, g2, bt2);

    // G4: S2 @ w2b + b2b, relu -> S0
    sgemm11<256, 128, 32, 1, 0><<<gB, blk, s32>>>(S2, w2b, nullptr, b2b, S0, nullptr);

    // G5: S0 @ lw1 + lb1, leaky -> S3
    sgemm11<128, 256, 64, 2, 0><<<gA, blk, s64>>>(S0, lw1, nullptr, lb1, S3, nullptr);

    // G6: S3 @ lw2 + lb2 -> S0
    sgemm11<256, 128, 32, 0, 0><<<gB, blk, s32>>>(S3, lw2, nullptr, lb2, S0, nullptr);

    // G7 (dual): S0 @ ew1_lo + eb1 -> S1 ; S0 @ ew1_hi -> S4
    sgemm11<128, 256, 64, 0, 1><<<gD, blk, s64>>>(S0, ew1, ew1 + 128 * HH, eb1, S1, S4);

    // Edge probabilities
    edge_k<<<dim3(32, 16), blk, EDGE_SMEM>>>(S1, S4, ew2, eb2, out);
}

// round 16
// speedup vs baseline: 1.0763x; 1.0238x over previous
#include <cuda_runtime.h>
#include <cuda_bf16.h>
#include <math.h>

// ---------------------------------------------------------------------------
// N=1024 nodes, F=128, H=256, complete graph.
//  - GIN aggregation on triu edges == inclusive prefix-sum over rows.
//  - cumsum(X) @ W == cumsum(X @ W)  -> GEMM first, scan after.
//  - leaky(relu(z)) == relu(z).
//  - Edge MLP: hidden = A[src] + B[dst], A = x@ew1[:F]+eb1, B = x@ew1[F:].
// R16 = R15 resubmit (broker flake, 3rd occurrence): MONOLITHIC-TILE GEMM —
//      whole A (32xK) and B (KxTN) panels staged via one cp.async burst;
//      ONE wait + ONE barrier; mainloop is pure LDS+FFMA2 straight-line code
//      with zero synchronization.
// ---------------------------------------------------------------------------

#define NN 1024
#define HH 256

__device__ float g_s0[NN * HH];
__device__ float g_s1[NN * HH];
__device__ float g_s2[NN * HH];
__device__ float g_s3[NN * HH];
__device__ float g_s4[NN * HH];

typedef unsigned long long u64;

// ---- packed f32x2 helpers (sm_100a) ---------------------------------------
__device__ __forceinline__ u64 add2(u64 a, u64 b) {
    u64 r; asm("add.rn.f32x2 %0, %1, %2;" : "=l"(r) : "l"(a), "l"(b)); return r;
}
__device__ __forceinline__ u64 fma2(u64 a, u64 b, u64 c) {
    u64 r; asm("fma.rn.f32x2 %0, %1, %2, %3;" : "=l"(r) : "l"(a), "l"(b), "l"(c)); return r;
}
__device__ __forceinline__ u64 relu2(u64 t) {
    unsigned lo, hi;
    asm("mov.b64 {%0, %1}, %2;" : "=r"(lo), "=r"(hi) : "l"(t));
    float flo = fmaxf(__uint_as_float(lo), 0.f);
    float fhi = fmaxf(__uint_as_float(hi), 0.f);
    u64 r;
    asm("mov.b64 %0, {%1, %2};" : "=l"(r)
        : "r"(__float_as_uint(flo)), "r"(__float_as_uint(fhi)));
    return r;
}
__device__ __forceinline__ float sum2(u64 t) {
    unsigned lo, hi;
    asm("mov.b64 {%0, %1}, %2;" : "=r"(lo), "=r"(hi) : "l"(t));
    return __uint_as_float(lo) + __uint_as_float(hi);
}
__device__ __forceinline__ u64 dup2(float a) {
    u64 r; unsigned u = __float_as_uint(a);
    asm("mov.b64 %0, {%1, %1};" : "=l"(r) : "r"(u));
    return r;
}
__device__ __forceinline__ void unpack2(u64 t, float& lo, float& hi) {
    unsigned a, b;
    asm("mov.b64 {%0, %1}, %2;" : "=r"(a), "=r"(b) : "l"(t));
    lo = __uint_as_float(a); hi = __uint_as_float(b);
}

// ---- cp.async helpers ------------------------------------------------------
__device__ __forceinline__ void cpa16(unsigned dst, const void* src) {
    asm volatile("cp.async.cg.shared.global [%0], [%1], 16;" :: "r"(dst), "l"(src));
}
#define CPA_COMMIT() asm volatile("cp.async.commit_group;")
#define CPA_WAIT0()  asm volatile("cp.async.wait_group 0;")

// ---------------------------------------------------------------------------
// GEMM v15 (monolithic tile): out[M,N] = X @ W (+bias)(+epilogue).
// 256 threads, TM=32, TN in {64,32}, micro 2x(TN/16), FFMA2.
// WHOLE A panel (32 x K) and B panel (K x TN) staged in ONE cp.async burst;
// single wait+barrier; mainloop has no synchronization at all.
// DUAL: blockIdx.z==1 -> X@W2 -> out2 (no bias). EPI: 0 none,1 relu,2 leaky.
// ---------------------------------------------------------------------------
template <int K, int N, int TN, int EPI, int DUAL>
__global__ __launch_bounds__(256) void sgemm15(
    const float* __restrict__ X, const float* __restrict__ W,
    const float* __restrict__ W2, const float* __restrict__ bias,
    float* __restrict__ out, float* __restrict__ out2) {

    constexpr int NJ2 = TN / 32;                  // u64 cols per thread (2|1)
    constexpr int ACH = (32 * K) / 1024;          // A float4 chunks / thread
    constexpr int BCH = (K * TN) / 1024;          // B float4 chunks / thread

    extern __shared__ float sh[];
    float* Asm = sh;                              // 32 x K (pitch K)
    float* Bsm = sh + 32 * K;                     // K x TN

    const int t  = threadIdx.x;
    const int tx = t & 15;
    const int ty = t >> 4;
    const int m0 = blockIdx.y * 32;
    const int n0 = blockIdx.x * TN;

    const float* Wp = W;
    const float* bp = bias;
    float*       op = out;
    if (DUAL && blockIdx.z) { Wp = W2; bp = nullptr; op = out2; }

    unsigned aSh = (unsigned)__cvta_generic_to_shared(Asm);
    unsigned bSh = (unsigned)__cvta_generic_to_shared(Bsm);

    // One burst: whole A panel + whole B panel.
#pragma unroll
    for (int p = 0; p < ACH; p++) {
        int q = t + 256 * p;
        int r = q / (K / 4);
        int c = (q % (K / 4)) * 4;
        cpa16(aSh + (unsigned)((r * K + c) * 4), &X[(m0 + r) * K + c]);
    }
#pragma unroll
    for (int p = 0; p < BCH; p++) {
        int q = t + 256 * p;
        int r = q / (TN / 4);
        int c = (q % (TN / 4)) * 4;
        cpa16(bSh + (unsigned)((r * TN + c) * 4), &Wp[r * N + n0 + c]);
    }
    CPA_COMMIT();
    CPA_WAIT0();
    __syncthreads();

    u64 acc[2][NJ2];
#pragma unroll
    for (int i = 0; i < 2; i++)
#pragma unroll
        for (int j = 0; j < NJ2; j++) acc[i][j] = 0ull;

    const float* Ar0 = &Asm[(ty * 2 + 0) * K];
    const float* Ar1 = &Asm[(ty * 2 + 1) * K];

#pragma unroll 8
    for (int k4 = 0; k4 < K; k4 += 4) {
        float4 a0v = *(const float4*)&Ar0[k4];
        float4 a1v = *(const float4*)&Ar1[k4];
#pragma unroll
        for (int kk = 0; kk < 4; kk++) {
            u64 a0d = dup2((&a0v.x)[kk]);
            u64 a1d = dup2((&a1v.x)[kk]);
            if (NJ2 == 2) {
                ulonglong2 b = *(const ulonglong2*)&Bsm[(k4 + kk) * TN + tx * 4];
                acc[0][0] = fma2(a0d, b.x, acc[0][0]);
                acc[0][1] = fma2(a0d, b.y, acc[0][1]);
                acc[1][0] = fma2(a1d, b.x, acc[1][0]);
                acc[1][1] = fma2(a1d, b.y, acc[1][1]);
            } else {
                u64 b = *(const u64*)&Bsm[(k4 + kk) * TN + tx * 2];
                acc[0][0] = fma2(a0d, b, acc[0][0]);
                acc[1][0] = fma2(a1d, b, acc[1][0]);
            }
        }
    }

    constexpr int CPT = NJ2 * 2;
#pragma unroll
    for (int i = 0; i < 2; i++) {
        int m = m0 + ty * 2 + i;
#pragma unroll
        for (int j = 0; j < NJ2; j++) {
            float v0, v1;
            unpack2(acc[i][j], v0, v1);
            int n = n0 + tx * CPT + j * 2;
            if (bp) { v0 += bp[n]; v1 += bp[n + 1]; }
            if (EPI == 1) { v0 = fmaxf(v0, 0.f); v1 = fmaxf(v1, 0.f); }
            if (EPI == 2) {
                v0 = (v0 >= 0.f) ? v0 : 0.01f * v0;
                v1 = (v1 >= 0.f) ? v1 : 0.01f * v1;
            }
            op[m * N + n]     = v0;
            op[m * N + n + 1] = v1;
        }
    }
}

#define G15_SMEM(K, TN) ((32 * (K) + (K) * (TN)) * 4)

// ---------------------------------------------------------------------------
// Column prefix-sum + BN + relu.
// ---------------------------------------------------------------------------
__global__ void cumsum_k(const float* __restrict__ in0, float* __restrict__ out,
                         const float* __restrict__ bias, const float* __restrict__ g,
                         const float* __restrict__ bt) {
    const int C = HH;
    const int c = blockIdx.x;
    const int t = threadIdx.x;
    __shared__ float ssum[256];

    float v[4];
    float run = 0.f;
    const int base = t * 4;
#pragma unroll
    for (int r = 0; r < 4; r++) {
        v[r] = in0[(base + r) * C + c];
        run += v[r];
        v[r] = run;
    }
    ssum[t] = run;
    __syncthreads();
    for (int off = 1; off < 256; off <<= 1) {
        float addv = 0.f;
        if (t >= off) addv = ssum[t - off];
        __syncthreads();
        if (t >= off) ssum[t] += addv;
        __syncthreads();
    }
    float excl = (t > 0) ? ssum[t - 1] : 0.f;
    float sc   = g[c] * rsqrtf(1.f + 1e-5f);
    float bb   = bias[c];
    float btc  = bt[c];
#pragma unroll
    for (int r = 0; r < 4; r++) {
        float h = (v[r] + excl + bb) * sc + btc;
        out[(base + r) * C + c] = fmaxf(h, 0.f);
    }
}

// ---------------------------------------------------------------------------
// Edge kernel (proven): 64x32 tile, 256 threads, 4x2 micro, stride-16,
// packed f32x2 + FMNMX relu. Active blocks: tj >= 2*ti.
// ---------------------------------------------------------------------------
#define ESA 256
#define ESB 260
#define EDGE_SMEM ((64 * ESA + 32 * ESB + 256) * 4)

__global__ __launch_bounds__(256) void edge_k(
    const float* __restrict__ A, const float* __restrict__ Bm,
    const float* __restrict__ ew2, const float* __restrict__ eb2,
    float* __restrict__ out) {
    const int ti = blockIdx.y, tj = blockIdx.x;
    if (tj < 2 * ti) return;

    extern __shared__ float sh[];
    float* As = sh;
    float* Bs = sh + 64 * ESA;
    float* ws = sh + 64 * ESA + 32 * ESB;

    const int t = threadIdx.x;
    ws[t] = ew2[t];

    const int i0 = ti * 64, j0 = tj * 32;
#pragma unroll
    for (int p = 0; p < 16; p++) {
        int q = t + 256 * p;
        int r = q >> 6;
        int c = (q & 63) << 2;
        *(float4*)&As[r * ESA + c] = *(const float4*)&A[(i0 + r) * HH + c];
    }
#pragma unroll
    for (int p = 0; p < 8; p++) {
        int q = t + 256 * p;
        int r = q >> 6;
        int c = (q & 63) << 2;
        *(float4*)&Bs[r * ESB + c] = *(const float4*)&Bm[(j0 + r) * HH + c];
    }
    __syncthreads();

    const int tx = t & 15, ty = t >> 4;

    u64 acc[4][2];
#pragma unroll
    for (int di = 0; di < 4; di++)
#pragma unroll
        for (int dj = 0; dj < 2; dj++) acc[di][dj] = 0ull;

#pragma unroll 2
    for (int h = 0; h < HH; h += 4) {
        u64 w01 = *(const u64*)&ws[h];
        u64 w23 = *(const u64*)&ws[h + 2];
        u64 a01[4], a23[4], b01[2], b23[2];
#pragma unroll
        for (int d = 0; d < 4; d++) {
            ulonglong2 av = *(const ulonglong2*)&As[(ty + 16 * d) * ESA + h];
            a01[d] = av.x; a23[d] = av.y;
        }
#pragma unroll
        for (int d = 0; d < 2; d++) {
            ulonglong2 bv = *(const ulonglong2*)&Bs[(tx + 16 * d) * ESB + h];
            b01[d] = bv.x; b23[d] = bv.y;
        }
#pragma unroll
        for (int di = 0; di < 4; di++) {
#pragma unroll
            for (int dj = 0; dj < 2; dj++) {
                acc[di][dj] = fma2(relu2(add2(a01[di], b01[dj])), w01, acc[di][dj]);
                acc[di][dj] = fma2(relu2(add2(a23[di], b23[dj])), w23, acc[di][dj]);
            }
        }
    }

    const float e2 = eb2[0];
#pragma unroll
    for (int di = 0; di < 4; di++) {
#pragma unroll
        for (int dj = 0; dj < 2; dj++) {
            int gi = i0 + ty + 16 * di;
            int gj = j0 + tx + 16 * dj;
            float s = sum2(acc[di][dj]) + e2;
            if (gi < gj) {
                float pv = 1.f / (1.f + __expf(-s));
                out[gi * NN + gj] = pv;
                out[gj * NN + gi] = pv;
            } else if (gi == gj) {
                out[gi * NN + gi] = 0.f;
            }
        }
    }
}

// ---------------------------------------------------------------------------
extern "C" void kernel_launch(void* const* d_in, const int* in_sizes, int n_in,
                              void* d_out, int out_size) {
    (void)in_sizes; (void)n_in; (void)out_size;
    const float* x0  = (const float*)d_in[0];
    const float* w1a = (const float*)d_in[1];
    const float* b1a = (const float*)d_in[2];
    const float* g1  = (const float*)d_in[3];
    const float* bt1 = (const float*)d_in[4];
    const float* w1b = (const float*)d_in[5];
    const float* b1b = (const float*)d_in[6];
    const float* w2a = (const float*)d_in[7];
    const float* b2a = (const float*)d_in[8];
    const float* g2  = (const float*)d_in[9];
    const float* bt2 = (const float*)d_in[10];
    const float* w2b = (const float*)d_in[11];
    const float* b2b = (const float*)d_in[12];
    const float* lw1 = (const float*)d_in[13];
    const float* lb1 = (const float*)d_in[14];
    const float* lw2 = (const float*)d_in[15];
    const float* lb2 = (const float*)d_in[16];
    const float* ew1 = (const float*)d_in[17];
    const float* eb1 = (const float*)d_in[18];
    const float* ew2 = (const float*)d_in[19];
    const float* eb2 = (const float*)d_in[20];
    float* out = (float*)d_out;

    float *S0, *S1, *S2, *S3, *S4;
    cudaGetSymbolAddress((void**)&S0, g_s0);
    cudaGetSymbolAddress((void**)&S1, g_s1);
    cudaGetSymbolAddress((void**)&S2, g_s2);
    cudaGetSymbolAddress((void**)&S3, g_s3);
    cudaGetSymbolAddress((void**)&S4, g_s4);

    const dim3 blk(256);
    const dim3 gA(4, 32);        // N=256 -> 128 blocks
    const dim3 gB(4, 32);        // N=128, TN=32 -> 128 blocks
    const dim3 gD(4, 32, 2);     // dual edge GEMM -> 256 blocks
    const int sK128N64 = G15_SMEM(128, 64);  // 48KB
    const int sK256N64 = G15_SMEM(256, 64);  // 96KB
    const int sK256N32 = G15_SMEM(256, 32);  // 64KB

    (void)cudaFuncSetAttribute((sgemm15<128, 256, 64, 0, 0>), cudaFuncAttributeMaxDynamicSharedMemorySize, sK128N64);
    (void)cudaFuncSetAttribute((sgemm15<256, 256, 64, 1, 0>), cudaFuncAttributeMaxDynamicSharedMemorySize, sK256N64);
    (void)cudaFuncSetAttribute((sgemm15<256, 256, 64, 0, 0>), cudaFuncAttributeMaxDynamicSharedMemorySize, sK256N64);
    (void)cudaFuncSetAttribute((sgemm15<256, 128, 32, 1, 0>), cudaFuncAttributeMaxDynamicSharedMemorySize, sK256N32);
    (void)cudaFuncSetAttribute((sgemm15<128, 256, 64, 2, 0>), cudaFuncAttributeMaxDynamicSharedMemorySize, sK128N64);
    (void)cudaFuncSetAttribute((sgemm15<256, 128, 32, 0, 0>), cudaFuncAttributeMaxDynamicSharedMemorySize, sK256N32);
    (void)cudaFuncSetAttribute((sgemm15<128, 256, 64, 0, 1>), cudaFuncAttributeMaxDynamicSharedMemorySize, sK128N64);
    (void)cudaFuncSetAttribute(edge_k, cudaFuncAttributeMaxDynamicSharedMemorySize, EDGE_SMEM);

    // G1: x0 @ w1a -> S0 ; cumsum+BN+relu -> S2
    sgemm15<128, 256, 64, 0, 0><<<gA, blk, sK128N64>>>(x0, w1a, nullptr, nullptr, S0, nullptr);
    cumsum_k<<<256, blk>>>(S0, S2, b1a, g1, bt1);

    // G2: S2 @ w1b + b1b, relu -> S0
    sgemm15<256, 256, 64, 1, 0><<<gA, blk, sK256N64>>>(S2, w1b, nullptr, b1b, S0, nullptr);

    // G3: S0 @ w2a -> S3 ; cumsum+BN+relu -> S2
    sgemm15<256, 256, 64, 0, 0><<<gA, blk, sK256N64>>>(S0, w2a, nullptr, nullptr, S3, nullptr);
    cumsum_k<<<256, blk>>>(S3, S2, b2a, g2, bt2);

    // G4: S2 @ w2b + b2b, relu -> S0
    sgemm15<256, 128, 32, 1, 0><<<gB, blk, sK256N32>>>(S2, w2b, nullptr, b2b, S0, nullptr);

    // G5: S0 @ lw1 + lb1, leaky -> S3
    sgemm15<128, 256, 64, 2, 0><<<gA, blk, sK128N64>>>(S0, lw1, nullptr, lb1, S3, nullptr);

    // G6: S3 @ lw2 + lb2 -> S0
    sgemm15<256, 128, 32, 0, 0><<<gB, blk, sK256N32>>>(S3, lw2, nullptr, lb2, S0, nullptr);

    // G7 (dual): S0 @ ew1_lo + eb1 -> S1 ; S0 @ ew1_hi -> S4
    sgemm15<128, 256, 64, 0, 1><<<gD, blk, sK128N64>>>(S0, ew1, ew1 + 128 * HH, eb1, S1, S4);

    // Edge probabilities
    edge_k<<<dim3(32, 16), blk, EDGE_SMEM>>>(S1, S4, ew2, eb2, out);
}

// round 17
// speedup vs baseline: 1.0789x; 1.0025x over previous
#include <cuda_runtime.h>
#include <cuda_bf16.h>
#include <math.h>

// ---------------------------------------------------------------------------
// N=1024 nodes, F=128, H=256, complete graph.
//  - GIN aggregation on triu edges == inclusive prefix-sum over rows.
//  - cumsum(X) @ W == cumsum(X @ W)  -> GEMM first, scan after.
//  - leaky(relu(z)) == relu(z).
//  - Edge MLP: hidden = A[src] + B[dst], A = x@ew1[:F]+eb1, B = x@ew1[F:].
// R17 = R16 monolithic-tile GEMM + EXPLICIT register double-buffering of the
//       LDS stream (R16 compiled to 32 regs -> no load hoisting -> exposed
//       29-cyc LDS latency; this forces ~64 regs and hides it).
// ---------------------------------------------------------------------------

#define NN 1024
#define HH 256

__device__ float g_s0[NN * HH];
__device__ float g_s1[NN * HH];
__device__ float g_s2[NN * HH];
__device__ float g_s3[NN * HH];
__device__ float g_s4[NN * HH];

typedef unsigned long long u64;

// ---- packed f32x2 helpers (sm_100a) ---------------------------------------
__device__ __forceinline__ u64 add2(u64 a, u64 b) {
    u64 r; asm("add.rn.f32x2 %0, %1, %2;" : "=l"(r) : "l"(a), "l"(b)); return r;
}
__device__ __forceinline__ u64 fma2(u64 a, u64 b, u64 c) {
    u64 r; asm("fma.rn.f32x2 %0, %1, %2, %3;" : "=l"(r) : "l"(a), "l"(b), "l"(c)); return r;
}
__device__ __forceinline__ u64 relu2(u64 t) {
    unsigned lo, hi;
    asm("mov.b64 {%0, %1}, %2;" : "=r"(lo), "=r"(hi) : "l"(t));
    float flo = fmaxf(__uint_as_float(lo), 0.f);
    float fhi = fmaxf(__uint_as_float(hi), 0.f);
    u64 r;
    asm("mov.b64 %0, {%1, %2};" : "=l"(r)
        : "r"(__float_as_uint(flo)), "r"(__float_as_uint(fhi)));
    return r;
}
__device__ __forceinline__ float sum2(u64 t) {
    unsigned lo, hi;
    asm("mov.b64 {%0, %1}, %2;" : "=r"(lo), "=r"(hi) : "l"(t));
    return __uint_as_float(lo) + __uint_as_float(hi);
}
__device__ __forceinline__ u64 dup2(float a) {
    u64 r; unsigned u = __float_as_uint(a);
    asm("mov.b64 %0, {%1, %1};" : "=l"(r) : "r"(u));
    return r;
}
__device__ __forceinline__ void unpack2(u64 t, float& lo, float& hi) {
    unsigned a, b;
    asm("mov.b64 {%0, %1}, %2;" : "=r"(a), "=r"(b) : "l"(t));
    lo = __uint_as_float(a); hi = __uint_as_float(b);
}

// ---- cp.async helpers ------------------------------------------------------
__device__ __forceinline__ void cpa16(unsigned dst, const void* src) {
    asm volatile("cp.async.cg.shared.global [%0], [%1], 16;" :: "r"(dst), "l"(src));
}
#define CPA_COMMIT() asm volatile("cp.async.commit_group;")
#define CPA_WAIT0()  asm volatile("cp.async.wait_group 0;")

// ---------------------------------------------------------------------------
// GEMM v16: monolithic tile + register-double-buffered LDS.
// 256 threads, TM=32, TN in {64,32}, micro 2x(TN/16), FFMA2.
// Whole A (32xK) and B (KxTN) staged in one cp.async burst; one barrier.
// Mainloop: while computing k-block (4 k) from reg buffer `cur`, the next
// k-block's LDS are issued into buffer `nxt` (~62 regs; hides 29-cyc LDS).
// DUAL: blockIdx.z==1 -> X@W2 -> out2 (no bias). EPI: 0 none,1 relu,2 leaky.
// ---------------------------------------------------------------------------
template <int K, int N, int TN, int EPI, int DUAL>
__global__ __launch_bounds__(256, 1) void sgemm16(
    const float* __restrict__ X, const float* __restrict__ W,
    const float* __restrict__ W2, const float* __restrict__ bias,
    float* __restrict__ out, float* __restrict__ out2) {

    constexpr int NJ2 = TN / 32;                  // u64 cols per thread (2|1)
    constexpr int ACH = (32 * K) / 1024;          // A float4 chunks / thread
    constexpr int BCH = (K * TN) / 1024;          // B float4 chunks / thread

    extern __shared__ float sh[];
    float* Asm = sh;                              // 32 x K (pitch K)
    float* Bsm = sh + 32 * K;                     // K x TN

    const int t  = threadIdx.x;
    const int tx = t & 15;
    const int ty = t >> 4;
    const int m0 = blockIdx.y * 32;
    const int n0 = blockIdx.x * TN;

    const float* Wp = W;
    const float* bp = bias;
    float*       op = out;
    if (DUAL && blockIdx.z) { Wp = W2; bp = nullptr; op = out2; }

    unsigned aSh = (unsigned)__cvta_generic_to_shared(Asm);
    unsigned bSh = (unsigned)__cvta_generic_to_shared(Bsm);

    // One burst: whole A panel + whole B panel.
#pragma unroll
    for (int p = 0; p < ACH; p++) {
        int q = t + 256 * p;
        int r = q / (K / 4);
        int c = (q % (K / 4)) * 4;
        cpa16(aSh + (unsigned)((r * K + c) * 4), &X[(m0 + r) * K + c]);
    }
#pragma unroll
    for (int p = 0; p < BCH; p++) {
        int q = t + 256 * p;
        int r = q / (TN / 4);
        int c = (q % (TN / 4)) * 4;
        cpa16(bSh + (unsigned)((r * TN + c) * 4), &Wp[r * N + n0 + c]);
    }
    CPA_COMMIT();
    CPA_WAIT0();
    __syncthreads();

    u64 acc[2][NJ2];
#pragma unroll
    for (int i = 0; i < 2; i++)
#pragma unroll
        for (int j = 0; j < NJ2; j++) acc[i][j] = 0ull;

    const float* Ar0 = &Asm[(ty * 2 + 0) * K];
    const float* Ar1 = &Asm[(ty * 2 + 1) * K];

    // Register double buffers: A rows (float4 per 4k) and B (per-kk vectors).
    float4 a0[2], a1[2];
    ulonglong2 b2v[2][4];                          // used when NJ2 == 2
    u64        b1v[2][4];                          // used when NJ2 == 1

    // preload k-block 0 into buffer 0
    a0[0] = *(const float4*)&Ar0[0];
    a1[0] = *(const float4*)&Ar1[0];
#pragma unroll
    for (int kk = 0; kk < 4; kk++) {
        if (NJ2 == 2) b2v[0][kk] = *(const ulonglong2*)&Bsm[kk * TN + tx * 4];
        else          b1v[0][kk] = *(const u64*)&Bsm[kk * TN + tx * 2];
    }

#pragma unroll 2
    for (int k4 = 0; k4 < K; k4 += 4) {
        const int cur = (k4 >> 2) & 1;
        const int nxt = cur ^ 1;
        // issue next block's loads first (latency hidden behind compute)
        if (k4 + 4 < K) {
            a0[nxt] = *(const float4*)&Ar0[k4 + 4];
            a1[nxt] = *(const float4*)&Ar1[k4 + 4];
#pragma unroll
            for (int kk = 0; kk < 4; kk++) {
                if (NJ2 == 2) b2v[nxt][kk] = *(const ulonglong2*)&Bsm[(k4 + 4 + kk) * TN + tx * 4];
                else          b1v[nxt][kk] = *(const u64*)&Bsm[(k4 + 4 + kk) * TN + tx * 2];
            }
        }
        // compute current block
#pragma unroll
        for (int kk = 0; kk < 4; kk++) {
            u64 a0d = dup2((&a0[cur].x)[kk]);
            u64 a1d = dup2((&a1[cur].x)[kk]);
            if (NJ2 == 2) {
                ulonglong2 b = b2v[cur][kk];
                acc[0][0] = fma2(a0d, b.x, acc[0][0]);
                acc[0][1] = fma2(a0d, b.y, acc[0][1]);
                acc[1][0] = fma2(a1d, b.x, acc[1][0]);
                acc[1][1] = fma2(a1d, b.y, acc[1][1]);
            } else {
                u64 b = b1v[cur][kk];
                acc[0][0] = fma2(a0d, b, acc[0][0]);
                acc[1][0] = fma2(a1d, b, acc[1][0]);
            }
        }
    }

    constexpr int CPT = NJ2 * 2;
#pragma unroll
    for (int i = 0; i < 2; i++) {
        int m = m0 + ty * 2 + i;
#pragma unroll
        for (int j = 0; j < NJ2; j++) {
            float v0, v1;
            unpack2(acc[i][j], v0, v1);
            int n = n0 + tx * CPT + j * 2;
            if (bp) { v0 += bp[n]; v1 += bp[n + 1]; }
            if (EPI == 1) { v0 = fmaxf(v0, 0.f); v1 = fmaxf(v1, 0.f); }
            if (EPI == 2) {
                v0 = (v0 >= 0.f) ? v0 : 0.01f * v0;
                v1 = (v1 >= 0.f) ? v1 : 0.01f * v1;
            }
            op[m * N + n]     = v0;
            op[m * N + n + 1] = v1;
        }
    }
}

#define G16_SMEM(K, TN) ((32 * (K) + (K) * (TN)) * 4)

// ---------------------------------------------------------------------------
// Column prefix-sum + BN + relu.
// ---------------------------------------------------------------------------
__global__ void cumsum_k(const float* __restrict__ in0, float* __restrict__ out,
                         const float* __restrict__ bias, const float* __restrict__ g,
                         const float* __restrict__ bt) {
    const int C = HH;
    const int c = blockIdx.x;
    const int t = threadIdx.x;
    __shared__ float ssum[256];

    float v[4];
    float run = 0.f;
    const int base = t * 4;
#pragma unroll
    for (int r = 0; r < 4; r++) {
        v[r] = in0[(base + r) * C + c];
        run += v[r];
        v[r] = run;
    }
    ssum[t] = run;
    __syncthreads();
    for (int off = 1; off < 256; off <<= 1) {
        float addv = 0.f;
        if (t >= off) addv = ssum[t - off];
        __syncthreads();
        if (t >= off) ssum[t] += addv;
        __syncthreads();
    }
    float excl = (t > 0) ? ssum[t - 1] : 0.f;
    float sc   = g[c] * rsqrtf(1.f + 1e-5f);
    float bb   = bias[c];
    float btc  = bt[c];
#pragma unroll
    for (int r = 0; r < 4; r++) {
        float h = (v[r] + excl + bb) * sc + btc;
        out[(base + r) * C + c] = fmaxf(h, 0.f);
    }
}

// ---------------------------------------------------------------------------
// Edge kernel (proven): 64x32 tile, 256 threads, 4x2 micro, stride-16,
// packed f32x2 + FMNMX relu. Active blocks: tj >= 2*ti.
// ---------------------------------------------------------------------------
#define ESA 256
#define ESB 260
#define EDGE_SMEM ((64 * ESA + 32 * ESB + 256) * 4)

__global__ __launch_bounds__(256) void edge_k(
    const float* __restrict__ A, const float* __restrict__ Bm,
    const float* __restrict__ ew2, const float* __restrict__ eb2,
    float* __restrict__ out) {
    const int ti = blockIdx.y, tj = blockIdx.x;
    if (tj < 2 * ti) return;

    extern __shared__ float sh[];
    float* As = sh;
    float* Bs = sh + 64 * ESA;
    float* ws = sh + 64 * ESA + 32 * ESB;

    const int t = threadIdx.x;
    ws[t] = ew2[t];

    const int i0 = ti * 64, j0 = tj * 32;
#pragma unroll
    for (int p = 0; p < 16; p++) {
        int q = t + 256 * p;
        int r = q >> 6;
        int c = (q & 63) << 2;
        *(float4*)&As[r * ESA + c] = *(const float4*)&A[(i0 + r) * HH + c];
    }
#pragma unroll
    for (int p = 0; p < 8; p++) {
        int q = t + 256 * p;
        int r = q >> 6;
        int c = (q & 63) << 2;
        *(float4*)&Bs[r * ESB + c] = *(const float4*)&Bm[(j0 + r) * HH + c];
    }
    __syncthreads();

    const int tx = t & 15, ty = t >> 4;

    u64 acc[4][2];
#pragma unroll
    for (int di = 0; di < 4; di++)
#pragma unroll
        for (int dj = 0; dj < 2; dj++) acc[di][dj] = 0ull;

#pragma unroll 2
    for (int h = 0; h < HH; h += 4) {
        u64 w01 = *(const u64*)&ws[h];
        u64 w23 = *(const u64*)&ws[h + 2];
        u64 a01[4], a23[4], b01[2], b23[2];
#pragma unroll
        for (int d = 0; d < 4; d++) {
            ulonglong2 av = *(const ulonglong2*)&As[(ty + 16 * d) * ESA + h];
            a01[d] = av.x; a23[d] = av.y;
        }
#pragma unroll
        for (int d = 0; d < 2; d++) {
            ulonglong2 bv = *(const ulonglong2*)&Bs[(tx + 16 * d) * ESB + h];
            b01[d] = bv.x; b23[d] = bv.y;
        }
#pragma unroll
        for (int di = 0; di < 4; di++) {
#pragma unroll
            for (int dj = 0; dj < 2; dj++) {
                acc[di][dj] = fma2(relu2(add2(a01[di], b01[dj])), w01, acc[di][dj]);
                acc[di][dj] = fma2(relu2(add2(a23[di], b23[dj])), w23, acc[di][dj]);
            }
        }
    }

    const float e2 = eb2[0];
#pragma unroll
    for (int di = 0; di < 4; di++) {
#pragma unroll
        for (int dj = 0; dj < 2; dj++) {
            int gi = i0 + ty + 16 * di;
            int gj = j0 + tx + 16 * dj;
            float s = sum2(acc[di][dj]) + e2;
            if (gi < gj) {
                float pv = 1.f / (1.f + __expf(-s));
                out[gi * NN + gj] = pv;
                out[gj * NN + gi] = pv;
            } else if (gi == gj) {
                out[gi * NN + gi] = 0.f;
            }
        }
    }
}

// ---------------------------------------------------------------------------
extern "C" void kernel_launch(void* const* d_in, const int* in_sizes, int n_in,
                              void* d_out, int out_size) {
    (void)in_sizes; (void)n_in; (void)out_size;
    const float* x0  = (const float*)d_in[0];
    const float* w1a = (const float*)d_in[1];
    const float* b1a = (const float*)d_in[2];
    const float* g1  = (const float*)d_in[3];
    const float* bt1 = (const float*)d_in[4];
    const float* w1b = (const float*)d_in[5];
    const float* b1b = (const float*)d_in[6];
    const float* w2a = (const float*)d_in[7];
    const float* b2a = (const float*)d_in[8];
    const float* g2  = (const float*)d_in[9];
    const float* bt2 = (const float*)d_in[10];
    const float* w2b = (const float*)d_in[11];
    const float* b2b = (const float*)d_in[12];
    const float* lw1 = (const float*)d_in[13];
    const float* lb1 = (const float*)d_in[14];
    const float* lw2 = (const float*)d_in[15];
    const float* lb2 = (const float*)d_in[16];
    const float* ew1 = (const float*)d_in[17];
    const float* eb1 = (const float*)d_in[18];
    const float* ew2 = (const float*)d_in[19];
    const float* eb2 = (const float*)d_in[20];
    float* out = (float*)d_out;

    float *S0, *S1, *S2, *S3, *S4;
    cudaGetSymbolAddress((void**)&S0, g_s0);
    cudaGetSymbolAddress((void**)&S1, g_s1);
    cudaGetSymbolAddress((void**)&S2, g_s2);
    cudaGetSymbolAddress((void**)&S3, g_s3);
    cudaGetSymbolAddress((void**)&S4, g_s4);

    const dim3 blk(256);
    const dim3 gA(4, 32);        // N=256 -> 128 blocks
    const dim3 gB(4, 32);        // N=128, TN=32 -> 128 blocks
    const dim3 gD(4, 32, 2);     // dual edge GEMM -> 256 blocks
    const int sK128N64 = G16_SMEM(128, 64);  // 48KB
    const int sK256N64 = G16_SMEM(256, 64);  // 96KB
    const int sK256N32 = G16_SMEM(256, 32);  // 64KB

    (void)cudaFuncSetAttribute((sgemm16<128, 256, 64, 0, 0>), cudaFuncAttributeMaxDynamicSharedMemorySize, sK128N64);
    (void)cudaFuncSetAttribute((sgemm16<256, 256, 64, 1, 0>), cudaFuncAttributeMaxDynamicSharedMemorySize, sK256N64);
    (void)cudaFuncSetAttribute((sgemm16<256, 256, 64, 0, 0>), cudaFuncAttributeMaxDynamicSharedMemorySize, sK256N64);
    (void)cudaFuncSetAttribute((sgemm16<256, 128, 32, 1, 0>), cudaFuncAttributeMaxDynamicSharedMemorySize, sK256N32);
    (void)cudaFuncSetAttribute((sgemm16<128, 256, 64, 2, 0>), cudaFuncAttributeMaxDynamicSharedMemorySize, sK128N64);
    (void)cudaFuncSetAttribute((sgemm16<256, 128, 32, 0, 0>), cudaFuncAttributeMaxDynamicSharedMemorySize, sK256N32);
    (void)cudaFuncSetAttribute((sgemm16<128, 256, 64, 0, 1>), cudaFuncAttributeMaxDynamicSharedMemorySize, sK128N64);
    (void)cudaFuncSetAttribute(edge_k, cudaFuncAttributeMaxDynamicSharedMemorySize, EDGE_SMEM);

    // G1: x0 @ w1a -> S0 ; cumsum+BN+relu -> S2
    sgemm16<128, 256, 64, 0, 0><<<gA, blk, sK128N64>>>(x0, w1a, nullptr, nullptr, S0, nullptr);
    cumsum_k<<<256, blk>>>(S0, S2, b1a, g1, bt1);

    // G2: S2 @ w1b + b1b, relu -> S0
    sgemm16<256, 256, 64, 1, 0><<<gA, blk, sK256N64>>>(S2, w1b, nullptr, b1b, S0, nullptr);

    // G3: S0 @ w2a -> S3 ; cumsum+BN+relu -> S2
    sgemm16<256, 256, 64, 0, 0><<<gA, blk, sK256N64>>>(S0, w2a, nullptr, nullptr, S3, nullptr);
    cumsum_k<<<256, blk>>>(S3, S2, b2a, g2, bt2);

    // G4: S2 @ w2b + b2b, relu -> S0
    sgemm16<256, 128, 32, 1, 0><<<gB, blk, sK256N32>>>(S2, w2b, nullptr, b2b, S0, nullptr);

    // G5: S0 @ lw1 + lb1, leaky -> S3
    sgemm16<128, 256, 64, 2, 0><<<gA, blk, sK128N64>>>(S0, lw1, nullptr, lb1, S3, nullptr);

    // G6: S3 @ lw2 + lb2 -> S0
    sgemm16<256, 128, 32, 0, 0><<<gB, blk, sK256N32>>>(S3, lw2, nullptr, lb2, S0, nullptr);

    // G7 (dual): S0 @ ew1_lo + eb1 -> S1 ; S0 @ ew1_hi -> S4
    sgemm16<128, 256, 64, 0, 1><<<gD, blk, sK128N64>>>(S0, ew1, ew1 + 128 * HH, eb1, S1, S4);

    // Edge probabilities
    edge_k<<<dim3(32, 16), blk, EDGE_SMEM>>>(S1, S4, ew2, eb2, out);
}